// round 1
// baseline (speedup 1.0000x reference)
#include <cuda_runtime.h>
#include <cuda_fp16.h>

// Problem constants (fixed by setup_inputs)
#define NE 8
#define NH 2048
#define NI 1408
#define NT 2048
#define NK 2
#define NG 128
#define NPAIR (NT * NK)      // 4096

#define BM 64                // token-pair tile
#define BI 64                // output tile (i or h)
#define BK 128               // k chunk == group size
#define MAXB ((NPAIR + BM - 1) / BM)   // 64 blocks worst case per expert

// ---------------- scratch ----------------
__device__ int   g_off[NE + 1];
__device__ int   g_pairs[NPAIR];                 // pair ids sorted by expert
__device__ float g_h[NPAIR][NI];                 // silu(g)*u per pair
__device__ float g_y[NPAIR][NH];                 // weighted down output per pair (indexed by ORIGINAL pair id)

// e2m1 nibble -> float, returns true_value / 16384 (fold 16384 into the group scale)
__device__ __forceinline__ float dec4(unsigned nib) {
    unsigned bits = ((nib & 7u) << 9) | ((nib & 8u) << 12);
    return __half2float(__ushort_as_half((unsigned short)bits));
}

// ---------------- routing ----------------
__global__ void k_route(const int* __restrict__ topk_idx) {
    __shared__ int s_cnt[NE];
    __shared__ int s_off[NE + 1];
    int tid = threadIdx.x;
    if (tid < NE) s_cnt[tid] = 0;
    __syncthreads();
    for (int p = tid; p < NPAIR; p += blockDim.x)
        atomicAdd(&s_cnt[topk_idx[p]], 1);
    __syncthreads();
    if (tid == 0) {
        int acc = 0;
        for (int e = 0; e < NE; e++) { s_off[e] = acc; acc += s_cnt[e]; s_cnt[e] = 0; }
        s_off[NE] = acc;
        for (int e = 0; e <= NE; e++) g_off[e] = s_off[e];
    }
    __syncthreads();
    for (int p = tid; p < NPAIR; p += blockDim.x) {
        int e   = topk_idx[p];
        int pos = s_off[e] + atomicAdd(&s_cnt[e], 1);
        g_pairs[pos] = p;
    }
}

// ---------------- gate/up + silu ----------------
__global__ __launch_bounds__(256) void k_gateup(
    const float*    __restrict__ x,
    const unsigned* __restrict__ gate_packed,
    const float*    __restrict__ gate_scales,
    const unsigned* __restrict__ up_packed,
    const float*    __restrict__ up_scales)
{
    int e  = blockIdx.y / MAXB;
    int mb = blockIdx.y % MAXB;
    int start = g_off[e], end = g_off[e + 1];
    int m0 = start + mb * BM;
    if (m0 >= end) return;
    int rows = min(BM, end - m0);
    int i0 = blockIdx.x * BI;

    __shared__ float    s_x[BM][BK + 1];
    __shared__ unsigned s_pg[BI][17];
    __shared__ unsigned s_pu[BI][17];
    __shared__ float    s_sg[BI];
    __shared__ float    s_su[BI];
    __shared__ int      s_tok[BM];
    __shared__ int      s_pair[BM];

    int tid = threadIdx.x;
    if (tid < BM) {
        int pr = g_pairs[m0 + ((tid < rows) ? tid : 0)];
        s_pair[tid] = (tid < rows) ? pr : -1;
        s_tok[tid]  = pr / NK;
    }
    __syncthreads();

    int tx = tid & 15, ty = tid >> 4;
    float ag[4][4], au[4][4];
    #pragma unroll
    for (int a = 0; a < 4; a++)
        #pragma unroll
        for (int b = 0; b < 4; b++) { ag[a][b] = 0.f; au[a][b] = 0.f; }

    const unsigned* gp = gate_packed + (size_t)e * NI * (NH / 8);
    const unsigned* up = up_packed   + (size_t)e * NI * (NH / 8);

    for (int c = 0; c < NH / BK; ++c) {
        // x tile: 64 rows x 128 cols (gathered rows)
        for (int l = tid; l < BM * (BK / 4); l += 256) {
            int r = l >> 5, c4 = l & 31;
            float4 v = *reinterpret_cast<const float4*>(
                x + (size_t)s_tok[r] * NH + c * BK + c4 * 4);
            s_x[r][c4 * 4 + 0] = v.x; s_x[r][c4 * 4 + 1] = v.y;
            s_x[r][c4 * 4 + 2] = v.z; s_x[r][c4 * 4 + 3] = v.w;
        }
        // packed weights: 64 rows x 16 words, each matrix
        for (int l = tid; l < BI * 16; l += 256) {
            int r = l >> 4, w = l & 15;
            size_t base = (size_t)(i0 + r) * (NH / 8) + c * 16 + w;
            s_pg[r][w] = gp[base];
            s_pu[r][w] = up[base];
        }
        if (tid < BI) {
            size_t sb = ((size_t)e * (NH / NG) + c) * NI + i0 + tid;
            s_sg[tid] = gate_scales[sb];
            s_su[tid] = up_scales[sb];
        }
        __syncthreads();

        float cg[4][4], cu[4][4];
        #pragma unroll
        for (int a = 0; a < 4; a++)
            #pragma unroll
            for (int b = 0; b < 4; b++) { cg[a][b] = 0.f; cu[a][b] = 0.f; }

        #pragma unroll 1
        for (int w = 0; w < 16; ++w) {
            unsigned pg[4], pu[4];
            #pragma unroll
            for (int ii = 0; ii < 4; ++ii) { pg[ii] = s_pg[tx + ii * 16][w]; pu[ii] = s_pu[tx + ii * 16][w]; }
            #pragma unroll
            for (int j = 0; j < 8; ++j) {
                float xv[4];
                #pragma unroll
                for (int tm = 0; tm < 4; ++tm) xv[tm] = s_x[ty + tm * 16][w * 8 + j];
                float wg[4], wu[4];
                #pragma unroll
                for (int ii = 0; ii < 4; ++ii) {
                    wg[ii] = dec4(pg[ii] >> (4 * j));
                    wu[ii] = dec4(pu[ii] >> (4 * j));
                }
                #pragma unroll
                for (int tm = 0; tm < 4; ++tm)
                    #pragma unroll
                    for (int ii = 0; ii < 4; ++ii) {
                        cg[tm][ii] += xv[tm] * wg[ii];
                        cu[tm][ii] += xv[tm] * wu[ii];
                    }
            }
        }
        #pragma unroll
        for (int ii = 0; ii < 4; ++ii) {
            float sg = s_sg[tx + ii * 16] * 16384.f;
            float su = s_su[tx + ii * 16] * 16384.f;
            #pragma unroll
            for (int tm = 0; tm < 4; ++tm) {
                ag[tm][ii] += cg[tm][ii] * sg;
                au[tm][ii] += cu[tm][ii] * su;
            }
        }
        __syncthreads();
    }

    #pragma unroll
    for (int tm = 0; tm < 4; ++tm) {
        int r = ty + tm * 16;
        if (r < rows) {
            int pr = s_pair[r];
            #pragma unroll
            for (int ii = 0; ii < 4; ++ii) {
                float g = ag[tm][ii], u = au[tm][ii];
                float hv = g / (1.f + __expf(-g)) * u;  // silu(g)*u
                g_h[pr][i0 + tx + ii * 16] = hv;
            }
        }
    }
}

// ---------------- down + topk weight ----------------
__global__ __launch_bounds__(256) void k_down(
    const unsigned* __restrict__ down_packed,
    const float*    __restrict__ down_scales,
    const float*    __restrict__ topk_w)
{
    int e  = blockIdx.y / MAXB;
    int mb = blockIdx.y % MAXB;
    int start = g_off[e], end = g_off[e + 1];
    int m0 = start + mb * BM;
    if (m0 >= end) return;
    int rows = min(BM, end - m0);
    int h0 = blockIdx.x * BI;

    __shared__ float    s_h[BM][BK + 1];
    __shared__ unsigned s_pd[BI][17];
    __shared__ float    s_sd[BI];
    __shared__ int      s_pair[BM];

    int tid = threadIdx.x;
    if (tid < BM)
        s_pair[tid] = g_pairs[m0 + ((tid < rows) ? tid : 0)];
    __syncthreads();

    int tx = tid & 15, ty = tid >> 4;
    float acc[4][4];
    #pragma unroll
    for (int a = 0; a < 4; a++)
        #pragma unroll
        for (int b = 0; b < 4; b++) acc[a][b] = 0.f;

    const unsigned* dp = down_packed + (size_t)e * NH * (NI / 8);

    for (int c = 0; c < NI / BK; ++c) {   // 11 chunks
        for (int l = tid; l < BM * (BK / 4); l += 256) {
            int r = l >> 5, c4 = l & 31;
            float4 v = *reinterpret_cast<const float4*>(&g_h[s_pair[r]][c * BK + c4 * 4]);
            s_h[r][c4 * 4 + 0] = v.x; s_h[r][c4 * 4 + 1] = v.y;
            s_h[r][c4 * 4 + 2] = v.z; s_h[r][c4 * 4 + 3] = v.w;
        }
        for (int l = tid; l < BI * 16; l += 256) {
            int r = l >> 4, w = l & 15;
            s_pd[r][w] = dp[(size_t)(h0 + r) * (NI / 8) + c * 16 + w];
        }
        if (tid < BI)
            s_sd[tid] = down_scales[((size_t)e * (NI / NG) + c) * NH + h0 + tid];
        __syncthreads();

        float ca[4][4];
        #pragma unroll
        for (int a = 0; a < 4; a++)
            #pragma unroll
            for (int b = 0; b < 4; b++) ca[a][b] = 0.f;

        #pragma unroll 1
        for (int w = 0; w < 16; ++w) {
            unsigned pd[4];
            #pragma unroll
            for (int ii = 0; ii < 4; ++ii) pd[ii] = s_pd[tx + ii * 16][w];
            #pragma unroll
            for (int j = 0; j < 8; ++j) {
                float hv[4];
                #pragma unroll
                for (int tm = 0; tm < 4; ++tm) hv[tm] = s_h[ty + tm * 16][w * 8 + j];
                float wd[4];
                #pragma unroll
                for (int ii = 0; ii < 4; ++ii) wd[ii] = dec4(pd[ii] >> (4 * j));
                #pragma unroll
                for (int tm = 0; tm < 4; ++tm)
                    #pragma unroll
                    for (int ii = 0; ii < 4; ++ii)
                        ca[tm][ii] += hv[tm] * wd[ii];
            }
        }
        #pragma unroll
        for (int ii = 0; ii < 4; ++ii) {
            float sd = s_sd[tx + ii * 16] * 16384.f;
            #pragma unroll
            for (int tm = 0; tm < 4; ++tm) acc[tm][ii] += ca[tm][ii] * sd;
        }
        __syncthreads();
    }

    #pragma unroll
    for (int tm = 0; tm < 4; ++tm) {
        int r = ty + tm * 16;
        if (r < rows) {
            int pr  = s_pair[r];
            float wgt = topk_w[pr];
            #pragma unroll
            for (int ii = 0; ii < 4; ++ii)
                g_y[pr][h0 + tx + ii * 16] = acc[tm][ii] * wgt;
        }
    }
}

// ---------------- combine K pairs per token ----------------
__global__ void k_combine(float* __restrict__ out) {
    int idx = blockIdx.x * blockDim.x + threadIdx.x;   // over T*H/4
    if (idx < NT * NH / 4) {
        int t  = idx / (NH / 4);
        int c4 = idx % (NH / 4);
        const float4 a = *reinterpret_cast<const float4*>(&g_y[t * NK + 0][c4 * 4]);
        const float4 b = *reinterpret_cast<const float4*>(&g_y[t * NK + 1][c4 * 4]);
        float4 r;
        r.x = a.x + b.x; r.y = a.y + b.y; r.z = a.z + b.z; r.w = a.w + b.w;
        *reinterpret_cast<float4*>(out + (size_t)idx * 4) = r;
    }
}

extern "C" void kernel_launch(void* const* d_in, const int* in_sizes, int n_in,
                              void* d_out, int out_size) {
    const float*    x           = (const float*)d_in[0];
    const unsigned* gate_packed = (const unsigned*)d_in[1];
    const float*    gate_scales = (const float*)d_in[2];
    const unsigned* up_packed   = (const unsigned*)d_in[3];
    const float*    up_scales   = (const float*)d_in[4];
    const unsigned* down_packed = (const unsigned*)d_in[5];
    const float*    down_scales = (const float*)d_in[6];
    const int*      topk_idx    = (const int*)d_in[7];
    const float*    topk_w      = (const float*)d_in[8];
    float*          out         = (float*)d_out;

    k_route<<<1, 256>>>(topk_idx);

    dim3 g1(NI / BI, NE * MAXB);
    k_gateup<<<g1, 256>>>(x, gate_packed, gate_scales, up_packed, up_scales);

    dim3 g2(NH / BI, NE * MAXB);
    k_down<<<g2, 256>>>(down_packed, down_scales, topk_w);

    int nelem4 = NT * NH / 4;
    k_combine<<<(nelem4 + 255) / 256, 256>>>(out);
}

// round 2
// speedup vs baseline: 3.2611x; 3.2611x over previous
#include <cuda_runtime.h>
#include <cstdint>

// Problem constants (fixed by setup_inputs)
#define NE 8
#define NH 2048
#define NI 1408
#define NT 2048
#define NK 2
#define NG 128
#define NPAIR (NT * NK)      // 4096

#define BM 64
#define MAXB (NPAIR / BM)    // 64

// ---------------- scratch ----------------
__device__ int   g_off[NE + 1];
__device__ int   g_pairs[NPAIR];
__device__ float g_h[NPAIR][NI];
__device__ float g_y[NPAIR][NH];

// ---------------- helpers ----------------
__device__ __forceinline__ unsigned f2tf(float f) {
    unsigned u;
    asm("cvt.rna.tf32.f32 %0, %1;" : "=r"(u) : "f"(f));
    return u;
}

__device__ __forceinline__ void mma8(float* c, const unsigned* a, const unsigned* b) {
    asm volatile(
        "mma.sync.aligned.m16n8k8.row.col.f32.tf32.tf32.f32 "
        "{%0,%1,%2,%3},{%4,%5,%6,%7},{%8,%9},{%0,%1,%2,%3};"
        : "+f"(c[0]), "+f"(c[1]), "+f"(c[2]), "+f"(c[3])
        : "r"(a[0]), "r"(a[1]), "r"(a[2]), "r"(a[3]), "r"(b[0]), "r"(b[1]));
}

// e2m1 nibble -> exact bf16 bit pattern of the raw value (no scale)
__device__ __forceinline__ unsigned short dec_bf16(unsigned nib) {
    unsigned t = nib & 7u;
    unsigned u = (t < 2u) ? t * 0x3f00u : 0x3f00u + (t << 6);   // 0,0.5 | 1,1.5,2,3,4,6
    u |= (nib & 8u) << 12;                                       // sign
    return (unsigned short)u;
}

// ---------------- routing ----------------
__global__ void k_route(const int* __restrict__ topk_idx) {
    __shared__ int s_cnt[NE];
    __shared__ int s_off[NE + 1];
    int tid = threadIdx.x;
    if (tid < NE) s_cnt[tid] = 0;
    __syncthreads();
    for (int p = tid; p < NPAIR; p += blockDim.x)
        atomicAdd(&s_cnt[topk_idx[p]], 1);
    __syncthreads();
    if (tid == 0) {
        int acc = 0;
        for (int e = 0; e < NE; e++) { s_off[e] = acc; acc += s_cnt[e]; s_cnt[e] = 0; }
        s_off[NE] = acc;
        for (int e = 0; e <= NE; e++) g_off[e] = s_off[e];
    }
    __syncthreads();
    for (int p = tid; p < NPAIR; p += blockDim.x) {
        int e   = topk_idx[p];
        int pos = s_off[e] + atomicAdd(&s_cnt[e], 1);
        g_pairs[pos] = p;
    }
}

// ---------------- gate/up GEMM (tf32 mma) + silu ----------------
__global__ __launch_bounds__(256, 2) void k_gateup(
    const float*    __restrict__ x,
    const unsigned* __restrict__ gp_,
    const float*    __restrict__ gs_,
    const unsigned* __restrict__ up_,
    const float*    __restrict__ us_)
{
    int e  = blockIdx.y / MAXB;
    int mb = blockIdx.y % MAXB;
    int start = g_off[e], end = g_off[e + 1];
    int m0 = start + mb * BM;
    if (m0 >= end) return;
    int rows = min(BM, end - m0);
    int i0 = blockIdx.x * 64;

    __shared__ __align__(16) unsigned       s_x[64][68];
    __shared__ __align__(16) unsigned short s_wg[64][72];
    __shared__ __align__(16) unsigned short s_wu[64][72];
    __shared__ int s_tok[BM];
    __shared__ int s_pair[BM];

    int tid = threadIdx.x;
    if (tid < BM) {
        int pr = g_pairs[m0 + (tid < rows ? tid : 0)];
        s_pair[tid] = pr;
        s_tok[tid]  = pr / NK;
    }
    __syncthreads();

    int lane = tid & 31, warp = tid >> 5;
    int wm = warp & 1, wn = warp >> 1;          // 2 m-warps x 4 n-warps
    int qrow = lane >> 2, qk = lane & 3;

    float ag[2][2][4] = {}, au[2][2][4] = {};
    float pg[2][2][4] = {}, pu[2][2][4] = {};

    const unsigned* gp = gp_ + (size_t)e * NI * (NH / 8);
    const unsigned* up = up_ + (size_t)e * NI * (NH / 8);

    for (int c = 0; c < NH / 64; ++c) {
        // stage x tile (tf32)
        #pragma unroll
        for (int i = 0; i < 4; ++i) {
            int l = tid + i * 256;
            int r = l >> 4, c4 = l & 15;
            float4 v = *reinterpret_cast<const float4*>(
                x + (size_t)s_tok[r] * NH + c * 64 + c4 * 4);
            uint4 t;
            t.x = f2tf(v.x); t.y = f2tf(v.y); t.z = f2tf(v.z); t.w = f2tf(v.w);
            *reinterpret_cast<uint4*>(&s_x[r][c4 * 4]) = t;
        }
        // stage + decode weights (raw e2m1 -> bf16, exact)
        #pragma unroll
        for (int i = 0; i < 4; ++i) {
            int l   = tid + i * 256;     // 0..1023
            int mat = l >> 9, r = (l >> 3) & 63, w = l & 7;
            const unsigned* src = mat ? up : gp;
            unsigned p = src[(size_t)(i0 + r) * (NH / 8) + c * 8 + w];
            unsigned short d[8];
            #pragma unroll
            for (int j = 0; j < 8; ++j) d[j] = dec_bf16((p >> (4 * j)) & 15u);
            uint4 t;
            t.x = d[0] | ((unsigned)d[1] << 16);
            t.y = d[2] | ((unsigned)d[3] << 16);
            t.z = d[4] | ((unsigned)d[5] << 16);
            t.w = d[6] | ((unsigned)d[7] << 16);
            unsigned short* dst = mat ? &s_wu[r][w * 8] : &s_wg[r][w * 8];
            *reinterpret_cast<uint4*>(dst) = t;
        }
        __syncthreads();

        #pragma unroll
        for (int kk = 0; kk < 8; ++kk) {
            int k0 = kk * 8;
            unsigned a[2][4];
            #pragma unroll
            for (int mi = 0; mi < 2; ++mi) {
                int mr = wm * 32 + mi * 16 + qrow;
                a[mi][0] = s_x[mr][k0 + qk];
                a[mi][1] = s_x[mr + 8][k0 + qk];
                a[mi][2] = s_x[mr][k0 + qk + 4];
                a[mi][3] = s_x[mr + 8][k0 + qk + 4];
            }
            #pragma unroll
            for (int ni = 0; ni < 2; ++ni) {
                int nr = wn * 16 + ni * 8 + qrow;
                unsigned bg[2], bu[2];
                bg[0] = (unsigned)s_wg[nr][k0 + qk] << 16;
                bg[1] = (unsigned)s_wg[nr][k0 + qk + 4] << 16;
                bu[0] = (unsigned)s_wu[nr][k0 + qk] << 16;
                bu[1] = (unsigned)s_wu[nr][k0 + qk + 4] << 16;
                #pragma unroll
                for (int mi = 0; mi < 2; ++mi) {
                    mma8(pg[mi][ni], a[mi], bg);
                    mma8(pu[mi][ni], a[mi], bu);
                }
            }
        }
        __syncthreads();

        if (c & 1) {   // end of a 128-wide group: apply group scales
            int g = c >> 1;
            const float* gsrow = gs_ + ((size_t)e * (NH / NG) + g) * NI;
            const float* usrow = us_ + ((size_t)e * (NH / NG) + g) * NI;
            #pragma unroll
            for (int ni = 0; ni < 2; ++ni) {
                int nb = i0 + wn * 16 + ni * 8 + (lane & 3) * 2;
                float sg0 = gsrow[nb], sg1 = gsrow[nb + 1];
                float su0 = usrow[nb], su1 = usrow[nb + 1];
                #pragma unroll
                for (int mi = 0; mi < 2; ++mi) {
                    ag[mi][ni][0] += pg[mi][ni][0] * sg0;
                    ag[mi][ni][1] += pg[mi][ni][1] * sg1;
                    ag[mi][ni][2] += pg[mi][ni][2] * sg0;
                    ag[mi][ni][3] += pg[mi][ni][3] * sg1;
                    au[mi][ni][0] += pu[mi][ni][0] * su0;
                    au[mi][ni][1] += pu[mi][ni][1] * su1;
                    au[mi][ni][2] += pu[mi][ni][2] * su0;
                    au[mi][ni][3] += pu[mi][ni][3] * su1;
                    #pragma unroll
                    for (int q = 0; q < 4; ++q) { pg[mi][ni][q] = 0.f; pu[mi][ni][q] = 0.f; }
                }
            }
        }
    }

    // epilogue: silu(g)*u
    #pragma unroll
    for (int mi = 0; mi < 2; ++mi) {
        #pragma unroll
        for (int q = 0; q < 4; ++q) {
            int r = wm * 32 + mi * 16 + qrow + ((q >= 2) ? 8 : 0);
            if (r < rows) {
                int pr = s_pair[r];
                #pragma unroll
                for (int ni = 0; ni < 2; ++ni) {
                    int col = i0 + wn * 16 + ni * 8 + (lane & 3) * 2 + (q & 1);
                    float g = ag[mi][ni][q], u = au[mi][ni][q];
                    g_h[pr][col] = g / (1.f + __expf(-g)) * u;
                }
            }
        }
    }
}

// ---------------- down GEMM (tf32 mma) + topk weight ----------------
__global__ __launch_bounds__(256, 2) void k_down(
    const unsigned* __restrict__ dp_,
    const float*    __restrict__ ds_,
    const float*    __restrict__ topk_w)
{
    int e  = blockIdx.y / MAXB;
    int mb = blockIdx.y % MAXB;
    int start = g_off[e], end = g_off[e + 1];
    int m0 = start + mb * BM;
    if (m0 >= end) return;
    int rows = min(BM, end - m0);
    int h0 = blockIdx.x * 64;

    __shared__ __align__(16) unsigned       s_h[64][68];
    __shared__ __align__(16) unsigned short s_wd[64][72];
    __shared__ int s_pair[BM];

    int tid = threadIdx.x;
    if (tid < BM)
        s_pair[tid] = g_pairs[m0 + (tid < rows ? tid : 0)];
    __syncthreads();

    int lane = tid & 31, warp = tid >> 5;
    int wm = warp & 1, wn = warp >> 1;
    int qrow = lane >> 2, qk = lane & 3;

    float ad[2][2][4] = {}, pd[2][2][4] = {};

    const unsigned* dp = dp_ + (size_t)e * NH * (NI / 8);

    for (int c = 0; c < NI / 64; ++c) {   // 22 stages
        #pragma unroll
        for (int i = 0; i < 4; ++i) {
            int l = tid + i * 256;
            int r = l >> 4, c4 = l & 15;
            float4 v = *reinterpret_cast<const float4*>(&g_h[s_pair[r]][c * 64 + c4 * 4]);
            uint4 t;
            t.x = f2tf(v.x); t.y = f2tf(v.y); t.z = f2tf(v.z); t.w = f2tf(v.w);
            *reinterpret_cast<uint4*>(&s_h[r][c4 * 4]) = t;
        }
        #pragma unroll
        for (int i = 0; i < 2; ++i) {
            int l = tid + i * 256;       // 0..511
            int r = l >> 3, w = l & 7;
            unsigned p = dp[(size_t)(h0 + r) * (NI / 8) + c * 8 + w];
            unsigned short d[8];
            #pragma unroll
            for (int j = 0; j < 8; ++j) d[j] = dec_bf16((p >> (4 * j)) & 15u);
            uint4 t;
            t.x = d[0] | ((unsigned)d[1] << 16);
            t.y = d[2] | ((unsigned)d[3] << 16);
            t.z = d[4] | ((unsigned)d[5] << 16);
            t.w = d[6] | ((unsigned)d[7] << 16);
            *reinterpret_cast<uint4*>(&s_wd[r][w * 8]) = t;
        }
        __syncthreads();

        #pragma unroll
        for (int kk = 0; kk < 8; ++kk) {
            int k0 = kk * 8;
            unsigned a[2][4];
            #pragma unroll
            for (int mi = 0; mi < 2; ++mi) {
                int mr = wm * 32 + mi * 16 + qrow;
                a[mi][0] = s_h[mr][k0 + qk];
                a[mi][1] = s_h[mr + 8][k0 + qk];
                a[mi][2] = s_h[mr][k0 + qk + 4];
                a[mi][3] = s_h[mr + 8][k0 + qk + 4];
            }
            #pragma unroll
            for (int ni = 0; ni < 2; ++ni) {
                int nr = wn * 16 + ni * 8 + qrow;
                unsigned bd[2];
                bd[0] = (unsigned)s_wd[nr][k0 + qk] << 16;
                bd[1] = (unsigned)s_wd[nr][k0 + qk + 4] << 16;
                #pragma unroll
                for (int mi = 0; mi < 2; ++mi)
                    mma8(pd[mi][ni], a[mi], bd);
            }
        }
        __syncthreads();

        if (c & 1) {
            int g = c >> 1;
            const float* dsrow = ds_ + ((size_t)e * (NI / NG) + g) * NH;
            #pragma unroll
            for (int ni = 0; ni < 2; ++ni) {
                int nb = h0 + wn * 16 + ni * 8 + (lane & 3) * 2;
                float s0 = dsrow[nb], s1 = dsrow[nb + 1];
                #pragma unroll
                for (int mi = 0; mi < 2; ++mi) {
                    ad[mi][ni][0] += pd[mi][ni][0] * s0;
                    ad[mi][ni][1] += pd[mi][ni][1] * s1;
                    ad[mi][ni][2] += pd[mi][ni][2] * s0;
                    ad[mi][ni][3] += pd[mi][ni][3] * s1;
                    #pragma unroll
                    for (int q = 0; q < 4; ++q) pd[mi][ni][q] = 0.f;
                }
            }
        }
    }

    #pragma unroll
    for (int mi = 0; mi < 2; ++mi) {
        #pragma unroll
        for (int q = 0; q < 4; ++q) {
            int r = wm * 32 + mi * 16 + qrow + ((q >= 2) ? 8 : 0);
            if (r < rows) {
                int pr = s_pair[r];
                float wgt = topk_w[pr];
                #pragma unroll
                for (int ni = 0; ni < 2; ++ni) {
                    int col = h0 + wn * 16 + ni * 8 + (lane & 3) * 2 + (q & 1);
                    g_y[pr][col] = ad[mi][ni][q] * wgt;
                }
            }
        }
    }
}

// ---------------- combine K pairs per token ----------------
__global__ void k_combine(float* __restrict__ out) {
    int idx = blockIdx.x * blockDim.x + threadIdx.x;
    if (idx < NT * NH / 4) {
        int t  = idx / (NH / 4);
        int c4 = idx % (NH / 4);
        const float4 a = *reinterpret_cast<const float4*>(&g_y[t * NK + 0][c4 * 4]);
        const float4 b = *reinterpret_cast<const float4*>(&g_y[t * NK + 1][c4 * 4]);
        float4 r;
        r.x = a.x + b.x; r.y = a.y + b.y; r.z = a.z + b.z; r.w = a.w + b.w;
        *reinterpret_cast<float4*>(out + (size_t)idx * 4) = r;
    }
}

extern "C" void kernel_launch(void* const* d_in, const int* in_sizes, int n_in,
                              void* d_out, int out_size) {
    const float*    x           = (const float*)d_in[0];
    const unsigned* gate_packed = (const unsigned*)d_in[1];
    const float*    gate_scales = (const float*)d_in[2];
    const unsigned* up_packed   = (const unsigned*)d_in[3];
    const float*    up_scales   = (const float*)d_in[4];
    const unsigned* down_packed = (const unsigned*)d_in[5];
    const float*    down_scales = (const float*)d_in[6];
    const int*      topk_idx    = (const int*)d_in[7];
    const float*    topk_w      = (const float*)d_in[8];
    float*          out         = (float*)d_out;

    k_route<<<1, 256>>>(topk_idx);

    dim3 g1(NI / 64, NE * MAXB);
    k_gateup<<<g1, 256>>>(x, gate_packed, gate_scales, up_packed, up_scales);

    dim3 g2(NH / 64, NE * MAXB);
    k_down<<<g2, 256>>>(down_packed, down_scales, topk_w);

    int nelem4 = NT * NH / 4;
    k_combine<<<(nelem4 + 255) / 256, 256>>>(out);
}

// round 4
// speedup vs baseline: 6.2974x; 1.9311x over previous
#include <cuda_runtime.h>
#include <cuda_fp16.h>
#include <cstdint>

// Problem constants
#define NE 8
#define NH 2048
#define NI 1408
#define NT 2048
#define NK 2
#define NG 128
#define NPAIR (NT * NK)   // 4096
#define BM 64
#define MB (NPAIR / BM)   // 64

// ---------------- scratch ----------------
__device__ int    g_off[NE + 1];
__device__ int    g_pairs[NPAIR];
__device__ __half g_h[NPAIR][NI];   // silu(g)*u / 32
__device__ float  g_y[NPAIR][NH];

// ---------------- helpers ----------------
__device__ __forceinline__ uint32_t smem_u32(const void* p) {
    uint32_t a;
    asm("{ .reg .u64 t; cvta.to.shared.u64 t, %1; cvt.u32.u64 %0, t; }" : "=r"(a) : "l"(p));
    return a;
}
__device__ __forceinline__ void ldsm4(unsigned* r, uint32_t addr) {
    asm volatile("ldmatrix.sync.aligned.m8n8.x4.shared.b16 {%0,%1,%2,%3},[%4];"
                 : "=r"(r[0]), "=r"(r[1]), "=r"(r[2]), "=r"(r[3]) : "r"(addr));
}
__device__ __forceinline__ void mma16816(float* c, const unsigned* a, const unsigned* b) {
    asm volatile(
        "mma.sync.aligned.m16n8k16.row.col.f32.f16.f16.f32 "
        "{%0,%1,%2,%3},{%4,%5,%6,%7},{%8,%9},{%0,%1,%2,%3};"
        : "+f"(c[0]), "+f"(c[1]), "+f"(c[2]), "+f"(c[3])
        : "r"(a[0]), "r"(a[1]), "r"(a[2]), "r"(a[3]), "r"(b[0]), "r"(b[1]));
}
// e2m1 nibble -> exact f32 value
__device__ __forceinline__ float dec_f32(unsigned nib) {
    unsigned t = nib & 7u;
    unsigned bits = (t < 2u) ? t * 0x3F000000u : 0x3F000000u + (t << 22);
    bits |= (nib & 8u) << 28;
    return __uint_as_float(bits);
}
// one packed word (8 nibbles) * fp32 scale -> 8 fp16 (one 16B chunk)
__device__ __forceinline__ uint4 dec_word(unsigned p, float sc) {
    unsigned h2[4];
    #pragma unroll
    for (int j = 0; j < 4; ++j) {
        float f0 = dec_f32((p >> (8 * j)) & 15u) * sc;
        float f1 = dec_f32((p >> (8 * j + 4)) & 15u) * sc;
        __half2 hh = __floats2half2_rn(f0, f1);
        h2[j] = *reinterpret_cast<unsigned*>(&hh);
    }
    return make_uint4(h2[0], h2[1], h2[2], h2[3]);
}
__device__ __forceinline__ uint4 f8_to_h8(float4 v0, float4 v1) {
    __half2 a = __floats2half2_rn(v0.x, v0.y);
    __half2 b = __floats2half2_rn(v0.z, v0.w);
    __half2 c = __floats2half2_rn(v1.x, v1.y);
    __half2 d = __floats2half2_rn(v1.z, v1.w);
    return make_uint4(*(unsigned*)&a, *(unsigned*)&b, *(unsigned*)&c, *(unsigned*)&d);
}

// ---------------- routing ----------------
__global__ void k_route(const int* __restrict__ topk_idx) {
    __shared__ int s_cnt[NE];
    __shared__ int s_off[NE + 1];
    int tid = threadIdx.x;
    if (tid < NE) s_cnt[tid] = 0;
    __syncthreads();
    for (int p = tid; p < NPAIR; p += blockDim.x)
        atomicAdd(&s_cnt[topk_idx[p]], 1);
    __syncthreads();
    if (tid == 0) {
        int acc = 0;
        for (int e = 0; e < NE; e++) { s_off[e] = acc; acc += s_cnt[e]; s_cnt[e] = 0; }
        s_off[NE] = acc;
        for (int e = 0; e <= NE; e++) g_off[e] = s_off[e];
    }
    __syncthreads();
    for (int p = tid; p < NPAIR; p += blockDim.x) {
        int e = topk_idx[p];
        int pos = s_off[e] + atomicAdd(&s_cnt[e], 1);
        g_pairs[pos] = p;
    }
}

// =========================================================================
// gate/up: M=64 pairs, N=128 (gate/up interleaved per i), K chunks of 64
// smem: A[2] 64x64 half (8KB each), B[2] 128x64 half (16KB each)
// =========================================================================
#define GU_SMEM (49152 + 512)

__global__ void __launch_bounds__(256, 2) k_gateup(
    const float*    __restrict__ x,
    const unsigned* __restrict__ gp_,
    const float*    __restrict__ gs_,
    const unsigned* __restrict__ up_,
    const float*    __restrict__ us_)
{
    int e = blockIdx.y / MB, mb = blockIdx.y % MB;
    int start = g_off[e], end = g_off[e + 1];
    int m0 = start + mb * BM;
    if (m0 >= end) return;
    int rows = min(BM, end - m0);
    int i0 = blockIdx.x * 64;

    extern __shared__ __align__(16) char smem[];
    uint32_t sb = smem_u32(smem);
    int* s_pair = (int*)(smem + 49152);
    int* s_tok  = (int*)(smem + 49152 + 256);

    int tid = threadIdx.x, warp = tid >> 5, lane = tid & 31;
    if (tid < BM) {
        int pr = g_pairs[m0 + (tid < rows ? tid : 0)];
        s_pair[tid] = pr;
        s_tok[tid]  = pr / NK;
    }
    __syncthreads();

    const unsigned* gp = gp_ + (size_t)e * NI * (NH / 8);
    const unsigned* up = up_ + (size_t)e * NI * (NH / 8);

    // staging roles
    int xr = tid >> 2, xcp = (tid & 3) * 2;         // x: row, chunk pair
    int wn_row = tid >> 1, wwb = (tid & 1) * 4;     // weights: B-row, word base
    int ig = i0 + (wn_row >> 1);
    const unsigned* wsrc = ((wn_row & 1) ? up : gp) + (size_t)ig * (NH / 8);
    const float*    ssrc = ((wn_row & 1) ? us_ : gs_) + (size_t)e * (NH / NG) * NI + ig;

    // mma roles
    int wm = warp & 1, wn = warp >> 1;
    float c[2][4][4];
    #pragma unroll
    for (int a = 0; a < 2; a++)
        #pragma unroll
        for (int b = 0; b < 4; b++)
            #pragma unroll
            for (int q = 0; q < 4; q++) c[a][b][q] = 0.f;

    float4 xv[4];
    uint4  wv;
    float  sc;

    // ---- prologue: load + store stage 0
    {
        const float* xp = x + (size_t)s_tok[xr] * NH + 0 * 64 + xcp * 8;
        xv[0] = *(const float4*)(xp);      xv[1] = *(const float4*)(xp + 4);
        xv[2] = *(const float4*)(xp + 8);  xv[3] = *(const float4*)(xp + 12);
        wv = *(const uint4*)(wsrc + 0 * 8 + wwb);
        sc = ssrc[0];
        uint32_t ab = sb, bb = sb + 16384;
        *(uint4*)(smem + (ab - sb) + xr * 128 + (((xcp)     ^ (xr & 7)) << 4)) = f8_to_h8(xv[0], xv[1]);
        *(uint4*)(smem + (ab - sb) + xr * 128 + (((xcp + 1) ^ (xr & 7)) << 4)) = f8_to_h8(xv[2], xv[3]);
        unsigned wds[4] = {wv.x, wv.y, wv.z, wv.w};
        #pragma unroll
        for (int j = 0; j < 4; ++j)
            *(uint4*)(smem + (bb - sb) + wn_row * 128 + (((wwb + j) ^ (wn_row & 7)) << 4)) = dec_word(wds[j], sc);
    }
    __syncthreads();

    for (int s = 0; s < NH / 64; ++s) {
        // prefetch stage s+1
        if (s + 1 < NH / 64) {
            const float* xp = x + (size_t)s_tok[xr] * NH + (s + 1) * 64 + xcp * 8;
            xv[0] = *(const float4*)(xp);      xv[1] = *(const float4*)(xp + 4);
            xv[2] = *(const float4*)(xp + 8);  xv[3] = *(const float4*)(xp + 12);
            wv = *(const uint4*)(wsrc + (s + 1) * 8 + wwb);
            sc = ssrc[(size_t)((s + 1) >> 1) * NI];
        }
        // mma on buf s&1
        {
            uint32_t ab = sb + (s & 1) * 8192;
            uint32_t bb = sb + 16384 + (s & 1) * 16384;
            #pragma unroll
            for (int kk = 0; kk < 4; ++kk) {
                int ch = kk * 2 + (lane >> 4);
                unsigned a0[4], a1[4];
                int r = wm * 32 + (lane & 15);
                ldsm4(a0, ab + r * 128 + ((ch ^ (r & 7)) << 4));
                r += 16;
                ldsm4(a1, ab + r * 128 + ((ch ^ (r & 7)) << 4));
                #pragma unroll
                for (int nj = 0; nj < 2; ++nj) {
                    unsigned bf[4];
                    int rb = wn * 32 + nj * 16 + (lane & 15);
                    ldsm4(bf, bb + rb * 128 + ((ch ^ (rb & 7)) << 4));
                    unsigned b0[2] = {bf[0], bf[2]}, b1[2] = {bf[1], bf[3]};
                    mma16816(c[0][nj * 2 + 0], a0, b0);
                    mma16816(c[0][nj * 2 + 1], a0, b1);
                    mma16816(c[1][nj * 2 + 0], a1, b0);
                    mma16816(c[1][nj * 2 + 1], a1, b1);
                }
            }
        }
        __syncthreads();
        if (s + 1 < NH / 64) {
            int nb = (s + 1) & 1;
            *(uint4*)(smem + nb * 8192 + xr * 128 + (((xcp)     ^ (xr & 7)) << 4)) = f8_to_h8(xv[0], xv[1]);
            *(uint4*)(smem + nb * 8192 + xr * 128 + (((xcp + 1) ^ (xr & 7)) << 4)) = f8_to_h8(xv[2], xv[3]);
            unsigned wds[4] = {wv.x, wv.y, wv.z, wv.w};
            #pragma unroll
            for (int j = 0; j < 4; ++j)
                *(uint4*)(smem + 16384 + nb * 16384 + wn_row * 128 + (((wwb + j) ^ (wn_row & 7)) << 4)) = dec_word(wds[j], sc);
            __syncthreads();
        }
    }

    // epilogue: c pairs are (gate, up) for one i
    int q = lane & 3, r0 = lane >> 2;
    #pragma unroll
    for (int mi = 0; mi < 2; ++mi) {
        int ra = wm * 32 + mi * 16 + r0;
        int rb = ra + 8;
        #pragma unroll
        for (int nf = 0; nf < 4; ++nf) {
            int ic = i0 + wn * 16 + nf * 4 + q;
            if (ra < rows) {
                float g = c[mi][nf][0], u = c[mi][nf][1];
                g_h[s_pair[ra]][ic] = __float2half_rn(g / (1.f + __expf(-g)) * u * 0.03125f);
            }
            if (rb < rows) {
                float g = c[mi][nf][2], u = c[mi][nf][3];
                g_h[s_pair[rb]][ic] = __float2half_rn(g / (1.f + __expf(-g)) * u * 0.03125f);
            }
        }
    }
}

// =========================================================================
// down: M=64 pairs, N=64 h-outputs, K chunks of 64 over NI=1408
// smem: A[2] 64x64 half (8KB), B[2] 64x64 half (8KB)
// =========================================================================
#define DN_SMEM (32768 + 256)

__global__ void __launch_bounds__(256, 2) k_down(
    const unsigned* __restrict__ dp_,
    const float*    __restrict__ ds_,
    const float*    __restrict__ topk_w)
{
    int e = blockIdx.y / MB, mb = blockIdx.y % MB;
    int start = g_off[e], end = g_off[e + 1];
    int m0 = start + mb * BM;
    if (m0 >= end) return;
    int rows = min(BM, end - m0);
    int h0 = blockIdx.x * 64;

    extern __shared__ __align__(16) char smem[];
    uint32_t sb = smem_u32(smem);
    int* s_pair = (int*)(smem + 32768);

    int tid = threadIdx.x, warp = tid >> 5, lane = tid & 31;
    if (tid < BM)
        s_pair[tid] = g_pairs[m0 + (tid < rows ? tid : 0)];
    __syncthreads();

    const unsigned* dp = dp_ + (size_t)e * NH * (NI / 8);

    int xr = tid >> 2, xcp = (tid & 3) * 2;
    bool do_w = tid < 128;
    int wn_row = tid >> 1, wwb = (tid & 1) * 4;
    const unsigned* wsrc = dp + (size_t)(h0 + wn_row) * (NI / 8);
    const float*    ssrc = ds_ + (size_t)e * (NI / NG) * NH + h0 + wn_row;

    int wm = warp & 1, wn = warp >> 1;
    float c[2][2][4];
    #pragma unroll
    for (int a = 0; a < 2; a++)
        #pragma unroll
        for (int b = 0; b < 2; b++)
            #pragma unroll
            for (int qq = 0; qq < 4; qq++) c[a][b][qq] = 0.f;

    uint4 av[2];
    uint4 wv;
    float sc;

    {
        const __half* hp = &g_h[s_pair[xr]][xcp * 8];
        av[0] = *(const uint4*)(hp);
        av[1] = *(const uint4*)(hp + 8);
        if (do_w) {
            wv = *(const uint4*)(wsrc + wwb);
            sc = ssrc[0];
        }
        *(uint4*)(smem + xr * 128 + (((xcp)     ^ (xr & 7)) << 4)) = av[0];
        *(uint4*)(smem + xr * 128 + (((xcp + 1) ^ (xr & 7)) << 4)) = av[1];
        if (do_w) {
            unsigned wds[4] = {wv.x, wv.y, wv.z, wv.w};
            #pragma unroll
            for (int j = 0; j < 4; ++j)
                *(uint4*)(smem + 16384 + wn_row * 128 + (((wwb + j) ^ (wn_row & 7)) << 4)) = dec_word(wds[j], sc);
        }
    }
    __syncthreads();

    for (int s = 0; s < NI / 64; ++s) {   // 22
        if (s + 1 < NI / 64) {
            const __half* hp = &g_h[s_pair[xr]][(s + 1) * 64 + xcp * 8];
            av[0] = *(const uint4*)(hp);
            av[1] = *(const uint4*)(hp + 8);
            if (do_w) {
                wv = *(const uint4*)(wsrc + (s + 1) * 8 + wwb);
                sc = ssrc[(size_t)((s + 1) >> 1) * NH];
            }
        }
        {
            uint32_t ab = sb + (s & 1) * 8192;
            uint32_t bb = sb + 16384 + (s & 1) * 8192;
            #pragma unroll
            for (int kk = 0; kk < 4; ++kk) {
                int ch = kk * 2 + (lane >> 4);
                unsigned a0[4], a1[4], bf[4];
                int r = wm * 32 + (lane & 15);
                ldsm4(a0, ab + r * 128 + ((ch ^ (r & 7)) << 4));
                r += 16;
                ldsm4(a1, ab + r * 128 + ((ch ^ (r & 7)) << 4));
                int rb = wn * 16 + (lane & 15);
                ldsm4(bf, bb + rb * 128 + ((ch ^ (rb & 7)) << 4));
                unsigned b0[2] = {bf[0], bf[2]}, b1[2] = {bf[1], bf[3]};
                mma16816(c[0][0], a0, b0);
                mma16816(c[0][1], a0, b1);
                mma16816(c[1][0], a1, b0);
                mma16816(c[1][1], a1, b1);
            }
        }
        __syncthreads();
        if (s + 1 < NI / 64) {
            int nb = (s + 1) & 1;
            *(uint4*)(smem + nb * 8192 + xr * 128 + (((xcp)     ^ (xr & 7)) << 4)) = av[0];
            *(uint4*)(smem + nb * 8192 + xr * 128 + (((xcp + 1) ^ (xr & 7)) << 4)) = av[1];
            if (do_w) {
                unsigned wds[4] = {wv.x, wv.y, wv.z, wv.w};
                #pragma unroll
                for (int j = 0; j < 4; ++j)
                    *(uint4*)(smem + 16384 + nb * 8192 + wn_row * 128 + (((wwb + j) ^ (wn_row & 7)) << 4)) = dec_word(wds[j], sc);
            }
            __syncthreads();
        }
    }

    int q = lane & 3, r0 = lane >> 2;
    #pragma unroll
    for (int mi = 0; mi < 2; ++mi) {
        int ra = wm * 32 + mi * 16 + r0;
        int rb = ra + 8;
        #pragma unroll
        for (int nf = 0; nf < 2; ++nf) {
            int col = h0 + wn * 16 + nf * 8 + 2 * q;
            if (ra < rows) {
                int pr = s_pair[ra];
                float w32 = topk_w[pr] * 32.f;
                g_y[pr][col]     = c[mi][nf][0] * w32;
                g_y[pr][col + 1] = c[mi][nf][1] * w32;
            }
            if (rb < rows) {
                int pr = s_pair[rb];
                float w32 = topk_w[pr] * 32.f;
                g_y[pr][col]     = c[mi][nf][2] * w32;
                g_y[pr][col + 1] = c[mi][nf][3] * w32;
            }
        }
    }
}

// ---------------- combine ----------------
__global__ void k_combine(float* __restrict__ out) {
    int idx = blockIdx.x * blockDim.x + threadIdx.x;
    if (idx < NT * NH / 4) {
        int t = idx / (NH / 4);
        int c4 = idx % (NH / 4);
        const float4 a = *reinterpret_cast<const float4*>(&g_y[t * NK + 0][c4 * 4]);
        const float4 b = *reinterpret_cast<const float4*>(&g_y[t * NK + 1][c4 * 4]);
        float4 r;
        r.x = a.x + b.x; r.y = a.y + b.y; r.z = a.z + b.z; r.w = a.w + b.w;
        *reinterpret_cast<float4*>(out + (size_t)idx * 4) = r;
    }
}

extern "C" void kernel_launch(void* const* d_in, const int* in_sizes, int n_in,
                              void* d_out, int out_size) {
    const float*    x           = (const float*)d_in[0];
    const unsigned* gate_packed = (const unsigned*)d_in[1];
    const float*    gate_scales = (const float*)d_in[2];
    const unsigned* up_packed   = (const unsigned*)d_in[3];
    const float*    up_scales   = (const float*)d_in[4];
    const unsigned* down_packed = (const unsigned*)d_in[5];
    const float*    down_scales = (const float*)d_in[6];
    const int*      topk_idx    = (const int*)d_in[7];
    const float*    topk_w      = (const float*)d_in[8];
    float*          out         = (float*)d_out;

    cudaFuncSetAttribute(k_gateup, cudaFuncAttributeMaxDynamicSharedMemorySize, GU_SMEM);
    cudaFuncSetAttribute(k_down,   cudaFuncAttributeMaxDynamicSharedMemorySize, DN_SMEM);

    k_route<<<1, 256>>>(topk_idx);

    dim3 g1(NI / 64, NE * MB);
    k_gateup<<<g1, 256, GU_SMEM>>>(x, gate_packed, gate_scales, up_packed, up_scales);

    dim3 g2(NH / 64, NE * MB);
    k_down<<<g2, 256, DN_SMEM>>>(down_packed, down_scales, topk_w);

    int nelem4 = NT * NH / 4;
    k_combine<<<(nelem4 + 255) / 256, 256>>>(out);
}

// round 5
// speedup vs baseline: 7.7343x; 1.2282x over previous
#include <cuda_runtime.h>
#include <cuda_fp16.h>
#include <cstdint>

// Problem constants
#define NE 8
#define NH 2048
#define NI 1408
#define NT 2048
#define NK 2
#define NG 128
#define NPAIR (NT * NK)   // 4096
#define BM 128
#define MB (NPAIR / BM)   // 32

// ---------------- scratch ----------------
__device__ int    g_off[NE + 1];
__device__ int    g_pairs[NPAIR];
__device__ __half g_xh[NT][NH];     // x in fp16
__device__ __half g_h[NPAIR][NI];   // silu(g)*u / 32
__device__ float  g_y[NPAIR][NH];

// ---------------- helpers ----------------
__device__ __forceinline__ uint32_t smem_u32(const void* p) {
    uint32_t a;
    asm("{ .reg .u64 t; cvta.to.shared.u64 t, %1; cvt.u32.u64 %0, t; }" : "=r"(a) : "l"(p));
    return a;
}
__device__ __forceinline__ void ldsm4(unsigned* r, uint32_t addr) {
    asm volatile("ldmatrix.sync.aligned.m8n8.x4.shared.b16 {%0,%1,%2,%3},[%4];"
                 : "=r"(r[0]), "=r"(r[1]), "=r"(r[2]), "=r"(r[3]) : "r"(addr));
}
__device__ __forceinline__ void mma16816(float* c, const unsigned* a, const unsigned* b) {
    asm volatile(
        "mma.sync.aligned.m16n8k16.row.col.f32.f16.f16.f32 "
        "{%0,%1,%2,%3},{%4,%5,%6,%7},{%8,%9},{%0,%1,%2,%3};"
        : "+f"(c[0]), "+f"(c[1]), "+f"(c[2]), "+f"(c[3])
        : "r"(a[0]), "r"(a[1]), "r"(a[2]), "r"(a[3]), "r"(b[0]), "r"(b[1]));
}
__device__ __forceinline__ void cp_async16(uint32_t dst, const void* src) {
    asm volatile("cp.async.cg.shared.global [%0], [%1], 16;" :: "r"(dst), "l"(src));
}
#define CP_COMMIT asm volatile("cp.async.commit_group;" ::: "memory")
#define CP_WAIT0  asm volatile("cp.async.wait_group 0;" ::: "memory")

// e2m1 nibble -> exact f32 value
__device__ __forceinline__ float dec_f32(unsigned nib) {
    unsigned t = nib & 7u;
    unsigned bits = (t < 2u) ? t * 0x3F000000u : 0x3F000000u + (t << 22);
    bits |= (nib & 8u) << 28;
    return __uint_as_float(bits);
}
// one packed word (8 nibbles) * fp32 scale -> 8 fp16
__device__ __forceinline__ uint4 dec_word(unsigned p, float sc) {
    unsigned h2[4];
    #pragma unroll
    for (int j = 0; j < 4; ++j) {
        float f0 = dec_f32((p >> (8 * j)) & 15u) * sc;
        float f1 = dec_f32((p >> (8 * j + 4)) & 15u) * sc;
        __half2 hh = __floats2half2_rn(f0, f1);
        h2[j] = *reinterpret_cast<unsigned*>(&hh);
    }
    return make_uint4(h2[0], h2[1], h2[2], h2[3]);
}
__device__ __forceinline__ uint4 f8_to_h8(float4 v0, float4 v1) {
    __half2 a = __floats2half2_rn(v0.x, v0.y);
    __half2 b = __floats2half2_rn(v0.z, v0.w);
    __half2 c = __floats2half2_rn(v1.x, v1.y);
    __half2 d = __floats2half2_rn(v1.z, v1.w);
    return make_uint4(*(unsigned*)&a, *(unsigned*)&b, *(unsigned*)&c, *(unsigned*)&d);
}

// ---------------- routing ----------------
__global__ void k_route(const int* __restrict__ topk_idx) {
    __shared__ int s_cnt[NE];
    __shared__ int s_off[NE + 1];
    int tid = threadIdx.x;
    if (tid < NE) s_cnt[tid] = 0;
    __syncthreads();
    for (int p = tid; p < NPAIR; p += blockDim.x)
        atomicAdd(&s_cnt[topk_idx[p]], 1);
    __syncthreads();
    if (tid == 0) {
        int acc = 0;
        for (int e = 0; e < NE; e++) { s_off[e] = acc; acc += s_cnt[e]; s_cnt[e] = 0; }
        s_off[NE] = acc;
        for (int e = 0; e <= NE; e++) g_off[e] = s_off[e];
    }
    __syncthreads();
    for (int p = tid; p < NPAIR; p += blockDim.x) {
        int e = topk_idx[p];
        int pos = s_off[e] + atomicAdd(&s_cnt[e], 1);
        g_pairs[pos] = p;
    }
}

// ---------------- x -> fp16 ----------------
__global__ void k_prep(const float* __restrict__ x) {
    int idx = blockIdx.x * blockDim.x + threadIdx.x;   // over NT*NH/8
    if (idx < NT * NH / 8) {
        const float4* p = reinterpret_cast<const float4*>(x) + (size_t)idx * 2;
        float4 v0 = p[0], v1 = p[1];
        *reinterpret_cast<uint4*>(&g_xh[0][0] + (size_t)idx * 8) = f8_to_h8(v0, v1);
    }
}

// =========================================================================
// gate/up: M=128 pairs, N=128 (64 i, gate/up interleaved), K chunks of 64
// smem: A[2] 128x64 half (16KB each), B[2] 128x64 half (16KB each)
// =========================================================================
#define GEMM_SMEM (65536 + 1024)

__global__ void __launch_bounds__(256, 2) k_gateup(
    const unsigned* __restrict__ gp_,
    const float*    __restrict__ gs_,
    const unsigned* __restrict__ up_,
    const float*    __restrict__ us_)
{
    int e = blockIdx.y / MB, mb = blockIdx.y % MB;
    int start = g_off[e], end = g_off[e + 1];
    int m0 = start + mb * BM;
    if (m0 >= end) return;
    int rows = min(BM, end - m0);
    int i0 = blockIdx.x * 64;

    extern __shared__ __align__(16) char smem[];
    uint32_t sb = smem_u32(smem);
    int* s_pair = (int*)(smem + 65536);
    int* s_tok  = (int*)(smem + 65536 + 512);

    int tid = threadIdx.x, warp = tid >> 5, lane = tid & 31;
    if (tid < BM) {
        int pr = g_pairs[m0 + (tid < rows ? tid : 0)];
        s_pair[tid] = pr;
        s_tok[tid]  = pr / NK;
    }
    __syncthreads();

    const unsigned* gp = gp_ + (size_t)e * NI * (NH / 8);
    const unsigned* up = up_ + (size_t)e * NI * (NH / 8);

    // staging roles: A row = tid>>1, chunks (tid&1)*4+j ; B row = tid>>1, words (tid&1)*4+j
    int ar = tid >> 1, ac = (tid & 1) * 4;
    const __half* asrc = &g_xh[s_tok[ar]][0];
    int wn_row = tid >> 1, wwb = (tid & 1) * 4;
    int ig = i0 + (wn_row >> 1);
    const unsigned* wsrc = ((wn_row & 1) ? up : gp) + (size_t)ig * (NH / 8);
    const float*    ssrc = ((wn_row & 1) ? us_ : gs_) + (size_t)e * (NH / NG) * NI + ig;
    uint32_t a_dst0 = sb + ar * 128;
    uint32_t b_dst0 = sb + 32768 + wn_row * 128;
    unsigned a_perm = ar & 7, b_perm = wn_row & 7;

    // mma roles: 4 m-warps x 2 n-warps
    int wm = warp & 3, wn = warp >> 2;
    float c[2][8][4];
    #pragma unroll
    for (int a = 0; a < 2; a++)
        #pragma unroll
        for (int b = 0; b < 8; b++)
            #pragma unroll
            for (int q = 0; q < 4; q++) c[a][b][q] = 0.f;

    uint4 wv;
    float sc;

    // ---- prologue: stage 0
    {
        #pragma unroll
        for (int j = 0; j < 4; ++j)
            cp_async16(a_dst0 + (((ac + j) ^ a_perm) << 4), asrc + (ac + j) * 8);
        CP_COMMIT;
        wv = *(const uint4*)(wsrc + wwb);
        sc = ssrc[0];
        unsigned wds[4] = {wv.x, wv.y, wv.z, wv.w};
        #pragma unroll
        for (int j = 0; j < 4; ++j)
            *(uint4*)(smem + 32768 + wn_row * 128 + (((wwb + j) ^ b_perm) << 4)) = dec_word(wds[j], sc);
        CP_WAIT0;
    }
    __syncthreads();

    const int S = NH / 64;   // 32
    for (int s = 0; s < S; ++s) {
        int nb = (s + 1) & 1;
        if (s + 1 < S) {
            #pragma unroll
            for (int j = 0; j < 4; ++j)
                cp_async16(a_dst0 + nb * 16384 + (((ac + j) ^ a_perm) << 4),
                           asrc + (s + 1) * 64 + (ac + j) * 8);
            CP_COMMIT;
            wv = *(const uint4*)(wsrc + (s + 1) * 8 + wwb);
            sc = ssrc[(size_t)((s + 1) >> 1) * NI];
        }
        // mma on buf s&1
        {
            uint32_t ab = sb + (s & 1) * 16384;
            uint32_t bb = sb + 32768 + (s & 1) * 16384;
            #pragma unroll
            for (int kk = 0; kk < 4; ++kk) {
                int ch = kk * 2 + (lane >> 4);
                unsigned a0[4], a1[4];
                int r = wm * 32 + (lane & 15);
                ldsm4(a0, ab + r * 128 + ((ch ^ (r & 7)) << 4));
                ldsm4(a1, ab + (r + 16) * 128 + ((ch ^ (r & 7)) << 4));
                #pragma unroll
                for (int nj = 0; nj < 4; ++nj) {
                    unsigned bf[4];
                    int rb = wn * 64 + nj * 16 + (lane & 15);
                    ldsm4(bf, bb + rb * 128 + ((ch ^ (rb & 7)) << 4));
                    unsigned b0[2] = {bf[0], bf[2]}, b1[2] = {bf[1], bf[3]};
                    mma16816(c[0][nj * 2 + 0], a0, b0);
                    mma16816(c[0][nj * 2 + 1], a0, b1);
                    mma16816(c[1][nj * 2 + 0], a1, b0);
                    mma16816(c[1][nj * 2 + 1], a1, b1);
                }
            }
        }
        if (s + 1 < S) {
            unsigned wds[4] = {wv.x, wv.y, wv.z, wv.w};
            #pragma unroll
            for (int j = 0; j < 4; ++j)
                *(uint4*)(smem + 32768 + nb * 16384 + wn_row * 128 + (((wwb + j) ^ b_perm) << 4)) = dec_word(wds[j], sc);
            CP_WAIT0;
        }
        __syncthreads();
    }

    // epilogue: (gate, up) pairs per i
    int q = lane & 3, r0 = lane >> 2;
    #pragma unroll
    for (int mi = 0; mi < 2; ++mi) {
        int ra  = wm * 32 + mi * 16 + r0;
        int rbr = ra + 8;
        #pragma unroll
        for (int nj = 0; nj < 4; ++nj) {
            #pragma unroll
            for (int hf = 0; hf < 2; ++hf) {
                int ic = i0 + wn * 32 + nj * 8 + hf * 4 + q;
                float* cc = c[mi][nj * 2 + hf];
                if (ra < rows) {
                    float g = cc[0], u = cc[1];
                    g_h[s_pair[ra]][ic] = __float2half_rn(g / (1.f + __expf(-g)) * u * 0.03125f);
                }
                if (rbr < rows) {
                    float g = cc[2], u = cc[3];
                    g_h[s_pair[rbr]][ic] = __float2half_rn(g / (1.f + __expf(-g)) * u * 0.03125f);
                }
            }
        }
    }
}

// =========================================================================
// down: M=128 pairs, N=128 h-outputs, K chunks of 64 over NI=1408
// =========================================================================
__global__ void __launch_bounds__(256, 2) k_down(
    const unsigned* __restrict__ dp_,
    const float*    __restrict__ ds_,
    const float*    __restrict__ topk_w)
{
    int e = blockIdx.y / MB, mb = blockIdx.y % MB;
    int start = g_off[e], end = g_off[e + 1];
    int m0 = start + mb * BM;
    if (m0 >= end) return;
    int rows = min(BM, end - m0);
    int h0 = blockIdx.x * 128;

    extern __shared__ __align__(16) char smem[];
    uint32_t sb = smem_u32(smem);
    int* s_pair = (int*)(smem + 65536);

    int tid = threadIdx.x, warp = tid >> 5, lane = tid & 31;
    if (tid < BM)
        s_pair[tid] = g_pairs[m0 + (tid < rows ? tid : 0)];
    __syncthreads();

    const unsigned* dp = dp_ + (size_t)e * NH * (NI / 8);

    int ar = tid >> 1, ac = (tid & 1) * 4;
    const __half* asrc = &g_h[s_pair[ar]][0];
    int wn_row = tid >> 1, wwb = (tid & 1) * 4;
    const unsigned* wsrc = dp + (size_t)(h0 + wn_row) * (NI / 8);
    const float*    ssrc = ds_ + (size_t)e * (NI / NG) * NH + h0 + wn_row;
    uint32_t a_dst0 = sb + ar * 128;
    unsigned a_perm = ar & 7, b_perm = wn_row & 7;

    int wm = warp & 3, wn = warp >> 2;
    float c[2][8][4];
    #pragma unroll
    for (int a = 0; a < 2; a++)
        #pragma unroll
        for (int b = 0; b < 8; b++)
            #pragma unroll
            for (int q = 0; q < 4; q++) c[a][b][q] = 0.f;

    uint4 wv;
    float sc;

    {
        #pragma unroll
        for (int j = 0; j < 4; ++j)
            cp_async16(a_dst0 + (((ac + j) ^ a_perm) << 4), asrc + (ac + j) * 8);
        CP_COMMIT;
        wv = *(const uint4*)(wsrc + wwb);
        sc = ssrc[0];
        unsigned wds[4] = {wv.x, wv.y, wv.z, wv.w};
        #pragma unroll
        for (int j = 0; j < 4; ++j)
            *(uint4*)(smem + 32768 + wn_row * 128 + (((wwb + j) ^ b_perm) << 4)) = dec_word(wds[j], sc);
        CP_WAIT0;
    }
    __syncthreads();

    const int S = NI / 64;   // 22
    for (int s = 0; s < S; ++s) {
        int nb = (s + 1) & 1;
        if (s + 1 < S) {
            #pragma unroll
            for (int j = 0; j < 4; ++j)
                cp_async16(a_dst0 + nb * 16384 + (((ac + j) ^ a_perm) << 4),
                           asrc + (s + 1) * 64 + (ac + j) * 8);
            CP_COMMIT;
            wv = *(const uint4*)(wsrc + (s + 1) * 8 + wwb);
            sc = ssrc[(size_t)((s + 1) >> 1) * NH];
        }
        {
            uint32_t ab = sb + (s & 1) * 16384;
            uint32_t bb = sb + 32768 + (s & 1) * 16384;
            #pragma unroll
            for (int kk = 0; kk < 4; ++kk) {
                int ch = kk * 2 + (lane >> 4);
                unsigned a0[4], a1[4];
                int r = wm * 32 + (lane & 15);
                ldsm4(a0, ab + r * 128 + ((ch ^ (r & 7)) << 4));
                ldsm4(a1, ab + (r + 16) * 128 + ((ch ^ (r & 7)) << 4));
                #pragma unroll
                for (int nj = 0; nj < 4; ++nj) {
                    unsigned bf[4];
                    int rb = wn * 64 + nj * 16 + (lane & 15);
                    ldsm4(bf, bb + rb * 128 + ((ch ^ (rb & 7)) << 4));
                    unsigned b0[2] = {bf[0], bf[2]}, b1[2] = {bf[1], bf[3]};
                    mma16816(c[0][nj * 2 + 0], a0, b0);
                    mma16816(c[0][nj * 2 + 1], a0, b1);
                    mma16816(c[1][nj * 2 + 0], a1, b0);
                    mma16816(c[1][nj * 2 + 1], a1, b1);
                }
            }
        }
        if (s + 1 < S) {
            unsigned wds[4] = {wv.x, wv.y, wv.z, wv.w};
            #pragma unroll
            for (int j = 0; j < 4; ++j)
                *(uint4*)(smem + 32768 + nb * 16384 + wn_row * 128 + (((wwb + j) ^ b_perm) << 4)) = dec_word(wds[j], sc);
            CP_WAIT0;
        }
        __syncthreads();
    }

    int q = lane & 3, r0 = lane >> 2;
    #pragma unroll
    for (int mi = 0; mi < 2; ++mi) {
        int ra  = wm * 32 + mi * 16 + r0;
        int rbr = ra + 8;
        #pragma unroll
        for (int nj = 0; nj < 4; ++nj) {
            #pragma unroll
            for (int hf = 0; hf < 2; ++hf) {
                int col = h0 + wn * 64 + nj * 16 + hf * 8 + 2 * q;
                float* cc = c[mi][nj * 2 + hf];
                if (ra < rows) {
                    int pr = s_pair[ra];
                    float w32 = topk_w[pr] * 32.f;
                    g_y[pr][col]     = cc[0] * w32;
                    g_y[pr][col + 1] = cc[1] * w32;
                }
                if (rbr < rows) {
                    int pr = s_pair[rbr];
                    float w32 = topk_w[pr] * 32.f;
                    g_y[pr][col]     = cc[2] * w32;
                    g_y[pr][col + 1] = cc[3] * w32;
                }
            }
        }
    }
}

// ---------------- combine ----------------
__global__ void k_combine(float* __restrict__ out) {
    int idx = blockIdx.x * blockDim.x + threadIdx.x;
    if (idx < NT * NH / 4) {
        int t = idx / (NH / 4);
        int c4 = idx % (NH / 4);
        const float4 a = *reinterpret_cast<const float4*>(&g_y[t * NK + 0][c4 * 4]);
        const float4 b = *reinterpret_cast<const float4*>(&g_y[t * NK + 1][c4 * 4]);
        float4 r;
        r.x = a.x + b.x; r.y = a.y + b.y; r.z = a.z + b.z; r.w = a.w + b.w;
        *reinterpret_cast<float4*>(out + (size_t)idx * 4) = r;
    }
}

extern "C" void kernel_launch(void* const* d_in, const int* in_sizes, int n_in,
                              void* d_out, int out_size) {
    const float*    x           = (const float*)d_in[0];
    const unsigned* gate_packed = (const unsigned*)d_in[1];
    const float*    gate_scales = (const float*)d_in[2];
    const unsigned* up_packed   = (const unsigned*)d_in[3];
    const float*    up_scales   = (const float*)d_in[4];
    const unsigned* down_packed = (const unsigned*)d_in[5];
    const float*    down_scales = (const float*)d_in[6];
    const int*      topk_idx    = (const int*)d_in[7];
    const float*    topk_w      = (const float*)d_in[8];
    float*          out         = (float*)d_out;

    cudaFuncSetAttribute(k_gateup, cudaFuncAttributeMaxDynamicSharedMemorySize, GEMM_SMEM);
    cudaFuncSetAttribute(k_down,   cudaFuncAttributeMaxDynamicSharedMemorySize, GEMM_SMEM);

    k_route<<<1, 256>>>(topk_idx);
    k_prep<<<(NT * NH / 8 + 255) / 256, 256>>>(x);

    dim3 g1(NI / 64, NE * MB);
    k_gateup<<<g1, 256, GEMM_SMEM>>>(gate_packed, gate_scales, up_packed, up_scales);

    dim3 g2(NH / 128, NE * MB);
    k_down<<<g2, 256, GEMM_SMEM>>>(down_packed, down_scales, topk_w);

    int nelem4 = NT * NH / 4;
    k_combine<<<(nelem4 + 255) / 256, 256>>>(out);
}

// round 6
// speedup vs baseline: 8.5119x; 1.1005x over previous
#include <cuda_runtime.h>
#include <cuda_fp16.h>
#include <cstdint>

// Problem constants
#define NE 8
#define NH 2048
#define NI 1408
#define NT 2048
#define NK 2
#define NG 128
#define NPAIR (NT * NK)   // 4096
#define BM 128
#define MB (NPAIR / BM)   // 32

// ---------------- scratch ----------------
__device__ int    g_off[NE + 1];
__device__ int    g_pairs[NPAIR];
__device__ __half g_xh[NT][NH];     // x in fp16
__device__ __half g_h[NPAIR][NI];   // silu(g)*u / 32
__device__ float  g_y[NPAIR][NH];

// ---------------- helpers ----------------
__device__ __forceinline__ uint32_t smem_u32(const void* p) {
    uint32_t a;
    asm("{ .reg .u64 t; cvta.to.shared.u64 t, %1; cvt.u32.u64 %0, t; }" : "=r"(a) : "l"(p));
    return a;
}
__device__ __forceinline__ void ldsm4(unsigned* r, uint32_t addr) {
    asm volatile("ldmatrix.sync.aligned.m8n8.x4.shared.b16 {%0,%1,%2,%3},[%4];"
                 : "=r"(r[0]), "=r"(r[1]), "=r"(r[2]), "=r"(r[3]) : "r"(addr));
}
__device__ __forceinline__ void mma16816(float* c, const unsigned* a, const unsigned* b) {
    asm volatile(
        "mma.sync.aligned.m16n8k16.row.col.f32.f16.f16.f32 "
        "{%0,%1,%2,%3},{%4,%5,%6,%7},{%8,%9},{%0,%1,%2,%3};"
        : "+f"(c[0]), "+f"(c[1]), "+f"(c[2]), "+f"(c[3])
        : "r"(a[0]), "r"(a[1]), "r"(a[2]), "r"(a[3]), "r"(b[0]), "r"(b[1]));
}
__device__ __forceinline__ void cp_async16(uint32_t dst, const void* src) {
    asm volatile("cp.async.cg.shared.global [%0], [%1], 16;" :: "r"(dst), "l"(src));
}
#define CP_COMMIT asm volatile("cp.async.commit_group;" ::: "memory")
#define CP_WAIT0  asm volatile("cp.async.wait_group 0;" ::: "memory")

// 8 e2m1 nibbles -> 8 fp16 encoding value * 2^-14 (exact, incl. subnormals).
__device__ __forceinline__ uint4 dec_word_raw(unsigned p) {
    unsigned e = p & 0x0F0F0F0Fu;
    unsigned o = (p >> 4) & 0x0F0F0F0Fu;
    uint4 r;
    unsigned u;
    u = __byte_perm(e, o, 0x0400);
    r.x = ((u & 0x00070007u) << 9) | ((u & 0x00080008u) << 12);
    u = __byte_perm(e, o, 0x0501);
    r.y = ((u & 0x00070007u) << 9) | ((u & 0x00080008u) << 12);
    u = __byte_perm(e, o, 0x0602);
    r.z = ((u & 0x00070007u) << 9) | ((u & 0x00080008u) << 12);
    u = __byte_perm(e, o, 0x0703);
    r.w = ((u & 0x00070007u) << 9) | ((u & 0x00080008u) << 12);
    return r;
}
__device__ __forceinline__ uint4 f8_to_h8(float4 v0, float4 v1) {
    __half2 a = __floats2half2_rn(v0.x, v0.y);
    __half2 b = __floats2half2_rn(v0.z, v0.w);
    __half2 c = __floats2half2_rn(v1.x, v1.y);
    __half2 d = __floats2half2_rn(v1.z, v1.w);
    return make_uint4(*(unsigned*)&a, *(unsigned*)&b, *(unsigned*)&c, *(unsigned*)&d);
}

// ---------------- routing ----------------
__global__ void k_route(const int* __restrict__ topk_idx) {
    __shared__ int s_cnt[NE];
    __shared__ int s_off[NE + 1];
    int tid = threadIdx.x;
    if (tid < NE) s_cnt[tid] = 0;
    __syncthreads();
    for (int p = tid; p < NPAIR; p += blockDim.x)
        atomicAdd(&s_cnt[topk_idx[p]], 1);
    __syncthreads();
    if (tid == 0) {
        int acc = 0;
        for (int e = 0; e < NE; e++) { s_off[e] = acc; acc += s_cnt[e]; s_cnt[e] = 0; }
        s_off[NE] = acc;
        for (int e = 0; e <= NE; e++) g_off[e] = s_off[e];
    }
    __syncthreads();
    for (int p = tid; p < NPAIR; p += blockDim.x) {
        int e = topk_idx[p];
        int pos = s_off[e] + atomicAdd(&s_cnt[e], 1);
        g_pairs[pos] = p;
    }
}

// ---------------- x -> fp16 ----------------
__global__ void k_prep(const float* __restrict__ x) {
    int idx = blockIdx.x * blockDim.x + threadIdx.x;
    if (idx < NT * NH / 8) {
        const float4* p = reinterpret_cast<const float4*>(x) + (size_t)idx * 2;
        float4 v0 = p[0], v1 = p[1];
        *reinterpret_cast<uint4*>(&g_xh[0][0] + (size_t)idx * 8) = f8_to_h8(v0, v1);
    }
}

// =========================================================================
// gate/up: M=128 pairs, N=128 (64 i, gate/up interleaved), K chunks of 64
// smem: A[2] 128x64 half (16KB each), B[2] 128x64 half (16KB each),
//       ratio table 16x128 f32 (8KB), pair/tok (1KB)
// =========================================================================
#define GU_SMEM (65536 + 8192 + 1024)
#define DN_SMEM (65536 + 5632 + 512)

__global__ void __launch_bounds__(256, 2) k_gateup(
    const unsigned* __restrict__ gp_,
    const float*    __restrict__ gs_,
    const unsigned* __restrict__ up_,
    const float*    __restrict__ us_)
{
    int e = blockIdx.y / MB, mb = blockIdx.y % MB;
    int start = g_off[e], end = g_off[e + 1];
    int m0 = start + mb * BM;
    if (m0 >= end) return;
    int rows = min(BM, end - m0);
    int i0 = blockIdx.x * 64;

    extern __shared__ __align__(16) char smem[];
    uint32_t sb = smem_u32(smem);
    float* rtab = (float*)(smem + 65536);
    int* s_pair = (int*)(smem + 65536 + 8192);
    int* s_tok  = (int*)(smem + 65536 + 8192 + 512);

    int tid = threadIdx.x, warp = tid >> 5, lane = tid & 31;
    if (tid < BM) {
        int pr = g_pairs[m0 + (tid < rows ? tid : 0)];
        s_pair[tid] = pr;
        s_tok[tid]  = pr / NK;
    }
    // ratio table: rtab[g*128+n] = s_g(n)/s_{g+1}(n), last group *= 16384
    for (int t = tid; t < 16 * 128; t += 256) {
        int g = t >> 7, n = t & 127;
        const float* arr = ((n & 1) ? us_ : gs_) + (size_t)e * 16 * NI + (i0 + (n >> 1));
        float sg = arr[(size_t)g * NI];
        rtab[t] = (g < 15) ? sg / arr[(size_t)(g + 1) * NI] : sg * 16384.f;
    }
    __syncthreads();

    const unsigned* gp = gp_ + (size_t)e * NI * (NH / 8);
    const unsigned* up = up_ + (size_t)e * NI * (NH / 8);

    // staging roles
    int ar = tid >> 1, ac = (tid & 1) * 4;
    const __half* asrc = &g_xh[s_tok[ar]][0];
    int wn_row = tid >> 1, wwb = (tid & 1) * 4;
    int ig = i0 + (wn_row >> 1);
    const unsigned* wsrc = ((wn_row & 1) ? up : gp) + (size_t)ig * (NH / 8);
    uint32_t a_dst0 = sb + ar * 128;
    unsigned a_perm = ar & 7, b_perm = wn_row & 7;

    // mma roles: 4 m-warps x 2 n-warps
    int wm = warp & 3, wn = warp >> 2;
    int q = lane & 3;
    float c[2][8][4];
    #pragma unroll
    for (int a = 0; a < 2; a++)
        #pragma unroll
        for (int b = 0; b < 8; b++)
            #pragma unroll
            for (int z = 0; z < 4; z++) c[a][b][z] = 0.f;

    uint4 wv;

    // prologue: stage 0
    {
        #pragma unroll
        for (int j = 0; j < 4; ++j)
            cp_async16(a_dst0 + (((ac + j) ^ a_perm) << 4), asrc + (ac + j) * 8);
        CP_COMMIT;
        wv = *(const uint4*)(wsrc + wwb);
        unsigned wds[4] = {wv.x, wv.y, wv.z, wv.w};
        #pragma unroll
        for (int j = 0; j < 4; ++j)
            *(uint4*)(smem + 32768 + wn_row * 128 + (((wwb + j) ^ b_perm) << 4)) = dec_word_raw(wds[j]);
        CP_WAIT0;
    }
    __syncthreads();

    const int S = NH / 64;   // 32
    for (int s = 0; s < S; ++s) {
        int nb = (s + 1) & 1;
        if (s + 1 < S) {
            #pragma unroll
            for (int j = 0; j < 4; ++j)
                cp_async16(a_dst0 + nb * 16384 + (((ac + j) ^ a_perm) << 4),
                           asrc + (s + 1) * 64 + (ac + j) * 8);
            CP_COMMIT;
            wv = *(const uint4*)(wsrc + (s + 1) * 8 + wwb);
        }
        // mma on buf s&1
        {
            uint32_t ab = sb + (s & 1) * 16384;
            uint32_t bb = sb + 32768 + (s & 1) * 16384;
            #pragma unroll
            for (int kk = 0; kk < 4; ++kk) {
                int ch = kk * 2 + (lane >> 4);
                unsigned a0[4], a1[4];
                int r = wm * 32 + (lane & 15);
                ldsm4(a0, ab + r * 128 + ((ch ^ (r & 7)) << 4));
                ldsm4(a1, ab + (r + 16) * 128 + ((ch ^ (r & 7)) << 4));
                #pragma unroll
                for (int nj = 0; nj < 4; ++nj) {
                    unsigned bf[4];
                    int rb = wn * 64 + nj * 16 + (lane & 15);
                    ldsm4(bf, bb + rb * 128 + ((ch ^ (rb & 7)) << 4));
                    unsigned b0[2] = {bf[0], bf[2]}, b1[2] = {bf[1], bf[3]};
                    mma16816(c[0][nj * 2 + 0], a0, b0);
                    mma16816(c[0][nj * 2 + 1], a0, b1);
                    mma16816(c[1][nj * 2 + 0], a1, b0);
                    mma16816(c[1][nj * 2 + 1], a1, b1);
                }
            }
        }
        // group-boundary rescale
        if (s & 1) {
            const float2* rt = (const float2*)(rtab + (s >> 1) * 128);
            #pragma unroll
            for (int nj = 0; nj < 4; ++nj)
                #pragma unroll
                for (int hf = 0; hf < 2; ++hf) {
                    float2 r2 = rt[(wn * 64 + nj * 16 + hf * 8 + 2 * q) >> 1];
                    float* c0 = c[0][nj * 2 + hf];
                    float* c1 = c[1][nj * 2 + hf];
                    c0[0] *= r2.x; c0[1] *= r2.y; c0[2] *= r2.x; c0[3] *= r2.y;
                    c1[0] *= r2.x; c1[1] *= r2.y; c1[2] *= r2.x; c1[3] *= r2.y;
                }
        }
        if (s + 1 < S) {
            unsigned wds[4] = {wv.x, wv.y, wv.z, wv.w};
            #pragma unroll
            for (int j = 0; j < 4; ++j)
                *(uint4*)(smem + 32768 + nb * 16384 + wn_row * 128 + (((wwb + j) ^ b_perm) << 4)) = dec_word_raw(wds[j]);
            CP_WAIT0;
        }
        __syncthreads();
    }

    // epilogue: (gate, up) pairs per i
    int r0 = lane >> 2;
    #pragma unroll
    for (int mi = 0; mi < 2; ++mi) {
        int ra  = wm * 32 + mi * 16 + r0;
        int rbr = ra + 8;
        #pragma unroll
        for (int nj = 0; nj < 4; ++nj) {
            #pragma unroll
            for (int hf = 0; hf < 2; ++hf) {
                int ic = i0 + wn * 32 + nj * 8 + hf * 4 + q;
                float* cc = c[mi][nj * 2 + hf];
                if (ra < rows) {
                    float g = cc[0], u = cc[1];
                    g_h[s_pair[ra]][ic] = __float2half_rn(g / (1.f + __expf(-g)) * u * 0.03125f);
                }
                if (rbr < rows) {
                    float g = cc[2], u = cc[3];
                    g_h[s_pair[rbr]][ic] = __float2half_rn(g / (1.f + __expf(-g)) * u * 0.03125f);
                }
            }
        }
    }
}

// =========================================================================
// down: M=128 pairs, N=128 h-outputs, K chunks of 64 over NI=1408
// =========================================================================
__global__ void __launch_bounds__(256, 2) k_down(
    const unsigned* __restrict__ dp_,
    const float*    __restrict__ ds_,
    const float*    __restrict__ topk_w)
{
    int e = blockIdx.y / MB, mb = blockIdx.y % MB;
    int start = g_off[e], end = g_off[e + 1];
    int m0 = start + mb * BM;
    if (m0 >= end) return;
    int rows = min(BM, end - m0);
    int h0 = blockIdx.x * 128;

    extern __shared__ __align__(16) char smem[];
    uint32_t sb = smem_u32(smem);
    float* rtab = (float*)(smem + 65536);
    int* s_pair = (int*)(smem + 65536 + 5632);

    int tid = threadIdx.x, warp = tid >> 5, lane = tid & 31;
    if (tid < BM)
        s_pair[tid] = g_pairs[m0 + (tid < rows ? tid : 0)];
    // ratio table: 11 groups; last group *= 16384*32 (h was stored /32)
    for (int t = tid; t < 11 * 128; t += 256) {
        int g = t >> 7, n = t & 127;
        const float* arr = ds_ + (size_t)e * 11 * NH + h0 + n;
        float sg = arr[(size_t)g * NH];
        rtab[t] = (g < 10) ? sg / arr[(size_t)(g + 1) * NH] : sg * (16384.f * 32.f);
    }
    __syncthreads();

    const unsigned* dp = dp_ + (size_t)e * NH * (NI / 8);

    int ar = tid >> 1, ac = (tid & 1) * 4;
    const __half* asrc = &g_h[s_pair[ar]][0];
    int wn_row = tid >> 1, wwb = (tid & 1) * 4;
    const unsigned* wsrc = dp + (size_t)(h0 + wn_row) * (NI / 8);
    uint32_t a_dst0 = sb + ar * 128;
    unsigned a_perm = ar & 7, b_perm = wn_row & 7;

    int wm = warp & 3, wn = warp >> 2;
    int q = lane & 3;
    float c[2][8][4];
    #pragma unroll
    for (int a = 0; a < 2; a++)
        #pragma unroll
        for (int b = 0; b < 8; b++)
            #pragma unroll
            for (int z = 0; z < 4; z++) c[a][b][z] = 0.f;

    uint4 wv;

    {
        #pragma unroll
        for (int j = 0; j < 4; ++j)
            cp_async16(a_dst0 + (((ac + j) ^ a_perm) << 4), asrc + (ac + j) * 8);
        CP_COMMIT;
        wv = *(const uint4*)(wsrc + wwb);
        unsigned wds[4] = {wv.x, wv.y, wv.z, wv.w};
        #pragma unroll
        for (int j = 0; j < 4; ++j)
            *(uint4*)(smem + 32768 + wn_row * 128 + (((wwb + j) ^ b_perm) << 4)) = dec_word_raw(wds[j]);
        CP_WAIT0;
    }
    __syncthreads();

    const int S = NI / 64;   // 22
    for (int s = 0; s < S; ++s) {
        int nb = (s + 1) & 1;
        if (s + 1 < S) {
            #pragma unroll
            for (int j = 0; j < 4; ++j)
                cp_async16(a_dst0 + nb * 16384 + (((ac + j) ^ a_perm) << 4),
                           asrc + (s + 1) * 64 + (ac + j) * 8);
            CP_COMMIT;
            wv = *(const uint4*)(wsrc + (s + 1) * 8 + wwb);
        }
        {
            uint32_t ab = sb + (s & 1) * 16384;
            uint32_t bb = sb + 32768 + (s & 1) * 16384;
            #pragma unroll
            for (int kk = 0; kk < 4; ++kk) {
                int ch = kk * 2 + (lane >> 4);
                unsigned a0[4], a1[4];
                int r = wm * 32 + (lane & 15);
                ldsm4(a0, ab + r * 128 + ((ch ^ (r & 7)) << 4));
                ldsm4(a1, ab + (r + 16) * 128 + ((ch ^ (r & 7)) << 4));
                #pragma unroll
                for (int nj = 0; nj < 4; ++nj) {
                    unsigned bf[4];
                    int rb = wn * 64 + nj * 16 + (lane & 15);
                    ldsm4(bf, bb + rb * 128 + ((ch ^ (rb & 7)) << 4));
                    unsigned b0[2] = {bf[0], bf[2]}, b1[2] = {bf[1], bf[3]};
                    mma16816(c[0][nj * 2 + 0], a0, b0);
                    mma16816(c[0][nj * 2 + 1], a0, b1);
                    mma16816(c[1][nj * 2 + 0], a1, b0);
                    mma16816(c[1][nj * 2 + 1], a1, b1);
                }
            }
        }
        if (s & 1) {
            const float2* rt = (const float2*)(rtab + (s >> 1) * 128);
            #pragma unroll
            for (int nj = 0; nj < 4; ++nj)
                #pragma unroll
                for (int hf = 0; hf < 2; ++hf) {
                    float2 r2 = rt[(wn * 64 + nj * 16 + hf * 8 + 2 * q) >> 1];
                    float* c0 = c[0][nj * 2 + hf];
                    float* c1 = c[1][nj * 2 + hf];
                    c0[0] *= r2.x; c0[1] *= r2.y; c0[2] *= r2.x; c0[3] *= r2.y;
                    c1[0] *= r2.x; c1[1] *= r2.y; c1[2] *= r2.x; c1[3] *= r2.y;
                }
        }
        if (s + 1 < S) {
            unsigned wds[4] = {wv.x, wv.y, wv.z, wv.w};
            #pragma unroll
            for (int j = 0; j < 4; ++j)
                *(uint4*)(smem + 32768 + nb * 16384 + wn_row * 128 + (((wwb + j) ^ b_perm) << 4)) = dec_word_raw(wds[j]);
            CP_WAIT0;
        }
        __syncthreads();
    }

    int r0 = lane >> 2;
    #pragma unroll
    for (int mi = 0; mi < 2; ++mi) {
        int ra  = wm * 32 + mi * 16 + r0;
        int rbr = ra + 8;
        #pragma unroll
        for (int nj = 0; nj < 4; ++nj) {
            #pragma unroll
            for (int hf = 0; hf < 2; ++hf) {
                int col = h0 + wn * 64 + nj * 16 + hf * 8 + 2 * q;
                float* cc = c[mi][nj * 2 + hf];
                if (ra < rows) {
                    int pr = s_pair[ra];
                    float w = topk_w[pr];
                    g_y[pr][col]     = cc[0] * w;
                    g_y[pr][col + 1] = cc[1] * w;
                }
                if (rbr < rows) {
                    int pr = s_pair[rbr];
                    float w = topk_w[pr];
                    g_y[pr][col]     = cc[2] * w;
                    g_y[pr][col + 1] = cc[3] * w;
                }
            }
        }
    }
}

// ---------------- combine ----------------
__global__ void k_combine(float* __restrict__ out) {
    int idx = blockIdx.x * blockDim.x + threadIdx.x;
    if (idx < NT * NH / 4) {
        int t = idx / (NH / 4);
        int c4 = idx % (NH / 4);
        const float4 a = *reinterpret_cast<const float4*>(&g_y[t * NK + 0][c4 * 4]);
        const float4 b = *reinterpret_cast<const float4*>(&g_y[t * NK + 1][c4 * 4]);
        float4 r;
        r.x = a.x + b.x; r.y = a.y + b.y; r.z = a.z + b.z; r.w = a.w + b.w;
        *reinterpret_cast<float4*>(out + (size_t)idx * 4) = r;
    }
}

extern "C" void kernel_launch(void* const* d_in, const int* in_sizes, int n_in,
                              void* d_out, int out_size) {
    const float*    x           = (const float*)d_in[0];
    const unsigned* gate_packed = (const unsigned*)d_in[1];
    const float*    gate_scales = (const float*)d_in[2];
    const unsigned* up_packed   = (const unsigned*)d_in[3];
    const float*    up_scales   = (const float*)d_in[4];
    const unsigned* down_packed = (const unsigned*)d_in[5];
    const float*    down_scales = (const float*)d_in[6];
    const int*      topk_idx    = (const int*)d_in[7];
    const float*    topk_w      = (const float*)d_in[8];
    float*          out         = (float*)d_out;

    cudaFuncSetAttribute(k_gateup, cudaFuncAttributeMaxDynamicSharedMemorySize, GU_SMEM);
    cudaFuncSetAttribute(k_down,   cudaFuncAttributeMaxDynamicSharedMemorySize, DN_SMEM);

    k_route<<<1, 256>>>(topk_idx);
    k_prep<<<(NT * NH / 8 + 255) / 256, 256>>>(x);

    dim3 g1(NI / 64, NE * MB);
    k_gateup<<<g1, 256, GU_SMEM>>>(gate_packed, gate_scales, up_packed, up_scales);

    dim3 g2(NH / 128, NE * MB);
    k_down<<<g2, 256, DN_SMEM>>>(down_packed, down_scales, topk_w);

    int nelem4 = NT * NH / 4;
    k_combine<<<(nelem4 + 255) / 256, 256>>>(out);
}